// round 6
// baseline (speedup 1.0000x reference)
#include <cuda_runtime.h>
#include <cuda_bf16.h>
#include <cstdint>

#define BATCH 16
#define SEQ   1024
#define FEAT  256
#define ROWS  (BATCH * SEQ)     // 16384
#define PJ    768               // 3 * FEAT (alpha | beta | uW)

// ---- scratch (__device__ globals; no allocation allowed) ----
// g_W rows [0,512): interleaved (row 2f = Wa[f], row 2f+1 = Wb[f]); [512,768): Wur
__device__ __align__(16) __nv_bfloat16 g_W   [PJ * FEAT];
__device__ __align__(16) __nv_bfloat16 g_xb  [ROWS * FEAT];     // x in bf16
__device__ __align__(16) __nv_bfloat16 g_proj[ROWS * PJ];       // [r][alpha|beta|uW]
__device__ __align__(16) __nv_bfloat16 g_Mt  [BATCH * FEAT * FEAT]; // Mt2[h][f]
__device__ float g_s [ROWS];
__device__ float g_br[FEAT];

// ---------------------------------------------------------------------------
__device__ __forceinline__ uint32_t smem_u32(const void* p) {
    return (uint32_t)__cvta_generic_to_shared(p);
}
__device__ __forceinline__ void cp16(void* s, const void* g) {
    asm volatile("cp.async.ca.shared.global [%0], [%1], 16;\n"
                 :: "r"(smem_u32(s)), "l"(g));
}
__device__ __forceinline__ void cp_commit() {
    asm volatile("cp.async.commit_group;\n");
}
__device__ __forceinline__ void cp_wait1() {
    asm volatile("cp.async.wait_group 1;\n");
}
__device__ __forceinline__ void mma_bf16(float c[4],
        uint32_t a0, uint32_t a1, uint32_t a2, uint32_t a3,
        uint32_t b0, uint32_t b1) {
    asm volatile(
        "mma.sync.aligned.m16n8k16.row.col.f32.bf16.bf16.f32 "
        "{%0,%1,%2,%3},{%4,%5,%6,%7},{%8,%9},{%0,%1,%2,%3};"
        : "+f"(c[0]), "+f"(c[1]), "+f"(c[2]), "+f"(c[3])
        : "r"(a0), "r"(a1), "r"(a2), "r"(a3), "r"(b0), "r"(b1));
}
__device__ __forceinline__ void ldm4(uint32_t r[4], const void* p) {
    asm volatile(
        "ldmatrix.sync.aligned.m8n8.x4.shared.b16 {%0,%1,%2,%3},[%4];"
        : "=r"(r[0]), "=r"(r[1]), "=r"(r[2]), "=r"(r[3])
        : "r"(smem_u32(p)));
}

// ---------------------------------------------------------------------------
// setup: one launch, independent block groups.
//  [0,2048)      x -> bf16 (8 elems/thread)
//  [2048,2112)   pack Wa/Wb interleaved into g_W rows [0,512)
//  [2112,2144)   Wur = W_r @ W_u (fp32 SIMT, 8 h-rows/block) -> g_W rows [512,768)
//  2144          br = W_r @ b
//  [2145,2161)   zero g_s
// ---------------------------------------------------------------------------
#define SETUP_BLOCKS 2161

__global__ __launch_bounds__(256)
void setup(const float* __restrict__ x,
           const float* __restrict__ Wa, const float* __restrict__ Wb,
           const float* __restrict__ Wu, const float* __restrict__ Wr,
           const float* __restrict__ bu,
           __nv_bfloat16* __restrict__ xb, __nv_bfloat16* __restrict__ W,
           float* __restrict__ br, float* __restrict__ s)
{
    const int blk = blockIdx.x, tid = threadIdx.x;
    if (blk < 2048) {
        int i = (blk * 256 + tid) * 8;
        float4 v0 = *(const float4*)(x + i);
        float4 v1 = *(const float4*)(x + i + 4);
        __nv_bfloat162 p0 = __floats2bfloat162_rn(v0.x, v0.y);
        __nv_bfloat162 p1 = __floats2bfloat162_rn(v0.z, v0.w);
        __nv_bfloat162 p2 = __floats2bfloat162_rn(v1.x, v1.y);
        __nv_bfloat162 p3 = __floats2bfloat162_rn(v1.z, v1.w);
        uint4 o = make_uint4(*(uint32_t*)&p0, *(uint32_t*)&p1,
                             *(uint32_t*)&p2, *(uint32_t*)&p3);
        *(uint4*)(xb + i) = o;
    } else if (blk < 2112) {
        // pack interleaved: packed row r (0..511): even -> Wa[r/2], odd -> Wb[r/2]
        int j0 = ((blk - 2048) * 256 + tid) * 8;    // [0, 131072)
        int row = j0 >> 8, col = j0 & 255;
        const float* src = ((row & 1) ? Wb : Wa) + (size_t)(row >> 1) * FEAT + col;
        float4 v0 = *(const float4*)src;
        float4 v1 = *(const float4*)(src + 4);
        __nv_bfloat162 p0 = __floats2bfloat162_rn(v0.x, v0.y);
        __nv_bfloat162 p1 = __floats2bfloat162_rn(v0.z, v0.w);
        __nv_bfloat162 p2 = __floats2bfloat162_rn(v1.x, v1.y);
        __nv_bfloat162 p3 = __floats2bfloat162_rn(v1.z, v1.w);
        uint4 o = make_uint4(*(uint32_t*)&p0, *(uint32_t*)&p1,
                             *(uint32_t*)&p2, *(uint32_t*)&p3);
        *(uint4*)(W + j0) = o;
    } else if (blk < 2144) {
        // Wur[h,f] = sum_g Wr[h,g] * Wu[g,f], 8 h-rows per block, thread = f
        __shared__ float sWr[8][FEAT];
        const int h0 = (blk - 2112) * 8;
        for (int k = 0; k < 8; k++)    // 8 rows x 256 floats, 256 threads
            sWr[k][tid] = Wr[(size_t)(h0 + k) * FEAT + tid];
        __syncthreads();
        float acc[8] = {};
        const int f = tid;
#pragma unroll 4
        for (int g = 0; g < FEAT; g++) {
            float wu = Wu[(size_t)g * FEAT + f];
#pragma unroll
            for (int h = 0; h < 8; h++)
                acc[h] += sWr[h][g] * wu;
        }
#pragma unroll
        for (int h = 0; h < 8; h++)
            W[(size_t)(512 + h0 + h) * FEAT + f] = __float2bfloat16(acc[h]);
    } else if (blk == 2144) {
        // br[h] = sum_g Wr[h,g] * bu[g]
        __shared__ float bsh[FEAT];
        bsh[tid] = bu[tid];
        __syncthreads();
        const float* wr = Wr + (size_t)tid * FEAT;
        float acc = 0.0f;
#pragma unroll 8
        for (int g = 0; g < FEAT; g += 4) {
            float4 w = *(const float4*)(wr + g);
            acc += w.x * bsh[g] + w.y * bsh[g + 1]
                 + w.z * bsh[g + 2] + w.w * bsh[g + 3];
        }
        br[tid] = acc;
    } else {
        int i = ((blk - 2145) * 256 + tid) * 4;
        *(float4*)(s + i) = make_float4(0.f, 0.f, 0.f, 0.f);
    }
}

// ---------------------------------------------------------------------------
// NT GEMM: C[M,N] = A[M,K] * B[N,K]^T, bf16 tensor core.
// BM=128, BN=128, BK=32, 256 threads, warp tile 64x32,
// 3-stage cp.async pipeline, ldmatrix fragment loads. smem dynamic 61440 B.
// EPI 1 (proj): cols<512 = interleaved alpha/beta -> scatter to canonical
//               layout + fused s[r]+=alpha.beta atomics; cols>=512 = uW + br.
// EPI 4 (final): (acc - s[r]*uW[r,c])/1024 + x[r,c], fp32 out.
// ---------------------------------------------------------------------------
#define NTSTG 5120   // elems per stage per operand (128*40)

template<int EPI, bool OUT_F32>
__global__ __launch_bounds__(256)
void gemm_nt(const __nv_bfloat16* __restrict__ A, int lda, long sA,
             const __nv_bfloat16* __restrict__ B, int ldb, long sB,
             void* __restrict__ Cp, int ldc, long sC, int K,
             const float* __restrict__ bias,
             float* __restrict__ sout,
             const float* __restrict__ sdot, long sS,
             const __nv_bfloat16* __restrict__ U, int ldu, long sU,
             const float* __restrict__ Xres, int ldx, long sX)
{
    extern __shared__ __align__(16) __nv_bfloat16 sm[];
    __nv_bfloat16* Ab = sm;
    __nv_bfloat16* Bb = sm + 3 * NTSTG;

    const int z = blockIdx.z;
    A += (size_t)z * sA;
    B += (size_t)z * sB;

    const int tid  = threadIdx.x;
    const int lane = tid & 31, warp = tid >> 5;
    const int wm = warp & 1, wn = warp >> 1;
    const int g = lane >> 2, t = lane & 3;
    const int row0 = blockIdx.y * 128, col0 = blockIdx.x * 128;

    const int lr = tid >> 1, lc = (tid & 1) * 16;

    const int aoff = (wm * 64 + (lane & 15)) * 40 + ((lane >> 4) << 3);
    const int boff = (wn * 32 + (lane & 7) + ((lane >> 3) & 1) * 8) * 40
                   + ((lane >> 4) << 3);

    float acc[4][4][4] = {};
    const int kIters = K / 32;

    const __nv_bfloat16* aSrc = A + (size_t)(row0 + lr) * lda + lc;
    const __nv_bfloat16* bSrc = B + (size_t)(col0 + lr) * ldb + lc;

#pragma unroll
    for (int s = 0; s < 2; s++) {
        if (s < kIters) {
            __nv_bfloat16* as = Ab + s * NTSTG + lr * 40 + lc;
            __nv_bfloat16* bs = Bb + s * NTSTG + lr * 40 + lc;
            cp16(as,     aSrc + s * 32);
            cp16(as + 8, aSrc + s * 32 + 8);
            cp16(bs,     bSrc + s * 32);
            cp16(bs + 8, bSrc + s * 32 + 8);
        }
        cp_commit();
    }

    for (int it = 0; it < kIters; it++) {
        cp_wait1();
        __syncthreads();
        if (it + 2 < kIters) {
            const int st = (it + 2) % 3;
            __nv_bfloat16* as = Ab + st * NTSTG + lr * 40 + lc;
            __nv_bfloat16* bs = Bb + st * NTSTG + lr * 40 + lc;
            cp16(as,     aSrc + (it + 2) * 32);
            cp16(as + 8, aSrc + (it + 2) * 32 + 8);
            cp16(bs,     bSrc + (it + 2) * 32);
            cp16(bs + 8, bSrc + (it + 2) * 32 + 8);
        }
        cp_commit();

        const int st = it % 3;
        const __nv_bfloat16* As = Ab + st * NTSTG;
        const __nv_bfloat16* Bs = Bb + st * NTSTG;
#pragma unroll
        for (int kc = 0; kc < 2; kc++) {
            uint32_t a[4][4];
#pragma unroll
            for (int i = 0; i < 4; i++)
                ldm4(a[i], As + aoff + i * 16 * 40 + kc * 16);
            uint32_t bm[2][4];
#pragma unroll
            for (int jp = 0; jp < 2; jp++)
                ldm4(bm[jp], Bs + boff + jp * 16 * 40 + kc * 16);
#pragma unroll
            for (int j = 0; j < 4; j++) {
                const uint32_t b0 = bm[j >> 1][j & 1];
                const uint32_t b1 = bm[j >> 1][(j & 1) + 2];
#pragma unroll
                for (int i = 0; i < 4; i++)
                    mma_bf16(acc[i][j], a[i][0], a[i][1], a[i][2], a[i][3], b0, b1);
            }
        }
    }

    // ---- epilogue ----
    const float invN = 1.0f / 1024.0f;
    const float* sd           = (EPI == 4) ? sdot + (size_t)z * sS : nullptr;
    const __nv_bfloat16* Uz   = (EPI == 4) ? U + (size_t)z * sU : nullptr;
    const float* Xz           = (EPI == 4) ? Xres + (size_t)z * sX : nullptr;
    float*          Cf = OUT_F32 ? (float*)Cp + (size_t)z * sC : nullptr;
    __nv_bfloat16*  Cb = OUT_F32 ? nullptr : (__nv_bfloat16*)Cp + (size_t)z * sC;

    if (EPI == 1 && col0 < 512) {
        // interleaved alpha/beta scatter + fused row-dot atomics
#pragma unroll
        for (int i = 0; i < 4; i++) {
            const int rb = row0 + wm * 64 + i * 16 + g;
            float pd0 = 0.0f, pd1 = 0.0f;
#pragma unroll
            for (int j = 0; j < 4; j++) {
                const int c = col0 + wn * 32 + j * 8 + t * 2;   // even
                const int f = c >> 1;
                float a0 = acc[i][j][0], b0v = acc[i][j][1];
                float a1 = acc[i][j][2], b1v = acc[i][j][3];
                pd0 += a0 * b0v;
                pd1 += a1 * b1v;
                Cb[(size_t)rb * ldc + f]             = __float2bfloat16(a0);
                Cb[(size_t)rb * ldc + 256 + f]       = __float2bfloat16(b0v);
                Cb[(size_t)(rb + 8) * ldc + f]       = __float2bfloat16(a1);
                Cb[(size_t)(rb + 8) * ldc + 256 + f] = __float2bfloat16(b1v);
            }
            pd0 += __shfl_xor_sync(0xFFFFFFFFu, pd0, 1);
            pd0 += __shfl_xor_sync(0xFFFFFFFFu, pd0, 2);
            pd1 += __shfl_xor_sync(0xFFFFFFFFu, pd1, 1);
            pd1 += __shfl_xor_sync(0xFFFFFFFFu, pd1, 2);
            if (t == 0) {
                atomicAdd(&sout[rb],     pd0);
                atomicAdd(&sout[rb + 8], pd1);
            }
        }
        return;
    }

#pragma unroll
    for (int i = 0; i < 4; i++) {
        const int rb = row0 + wm * 64 + i * 16 + g;
#pragma unroll
        for (int j = 0; j < 4; j++) {
            const int c = col0 + wn * 32 + j * 8 + t * 2;
            float v00 = acc[i][j][0], v01 = acc[i][j][1];
            float v10 = acc[i][j][2], v11 = acc[i][j][3];
            if (EPI == 1) {
                // uW columns: add br
                float b0 = bias[c - 512], b1 = bias[c - 511];
                v00 += b0; v01 += b1; v10 += b0; v11 += b1;
            } else if (EPI == 4) {
                float s0 = sd[rb], s1 = sd[rb + 8];
                __nv_bfloat162 u0 = *(const __nv_bfloat162*)(Uz + (size_t)rb * ldu + c);
                __nv_bfloat162 u1 = *(const __nv_bfloat162*)(Uz + (size_t)(rb + 8) * ldu + c);
                float2 fu0 = __bfloat1622float2(u0);
                float2 fu1 = __bfloat1622float2(u1);
                float2 x0 = *(const float2*)(Xz + (size_t)rb * ldx + c);
                float2 x1 = *(const float2*)(Xz + (size_t)(rb + 8) * ldx + c);
                v00 = (v00 - s0 * fu0.x) * invN + x0.x;
                v01 = (v01 - s0 * fu0.y) * invN + x0.y;
                v10 = (v10 - s1 * fu1.x) * invN + x1.x;
                v11 = (v11 - s1 * fu1.y) * invN + x1.y;
            }
            if (OUT_F32) {
                *(float2*)(Cf + (size_t)rb * ldc + c)       = make_float2(v00, v01);
                *(float2*)(Cf + (size_t)(rb + 8) * ldc + c) = make_float2(v10, v11);
            } else {
                *(__nv_bfloat162*)(Cb + (size_t)rb * ldc + c)       = __floats2bfloat162_rn(v00, v01);
                *(__nv_bfloat162*)(Cb + (size_t)(rb + 8) * ldc + c) = __floats2bfloat162_rn(v10, v11);
            }
        }
    }
}

// ---------------------------------------------------------------------------
// TT GEMM: C[m,n] = sum_k A[k][m] * B[k][n], operands stored [K][*].
// BM=64, BN=64, BK=32, 256 thr, warps 2m x 4n, ldmatrix.trans, 3-stage cp.async.
// ---------------------------------------------------------------------------
__global__ __launch_bounds__(256)
void gemm_tt(const __nv_bfloat16* __restrict__ A, int lda, long sA,
             const __nv_bfloat16* __restrict__ B, int ldb, long sB,
             __nv_bfloat16* __restrict__ C, int ldc, long sC, int K)
{
    const int z = blockIdx.z;
    A += (size_t)z * sA; B += (size_t)z * sB; C += (size_t)z * sC;

    __shared__ __align__(16) __nv_bfloat16 SA[3][32][72];
    __shared__ __align__(16) __nv_bfloat16 SB[3][32][72];

    const int tid = threadIdx.x, lane = tid & 31, warp = tid >> 5;
    const int wm = warp >> 2, wn = warp & 3;
    const int m0 = blockIdx.y * 64, n0 = blockIdx.x * 64;

    const int lr = tid >> 3, lc = (tid & 7) * 8;

    float acc[2][2][4] = {};

    const int arow = ((lane >> 4) << 3) + (lane & 7);
    const int acol = ((lane >> 3) & 1) << 3;
    const int brow = (((lane >> 3) & 1) << 3) + (lane & 7);

    const __nv_bfloat16* aSrc = A + (size_t)lr * lda + m0 + lc;
    const __nv_bfloat16* bSrc = B + (size_t)lr * ldb + n0 + lc;
    const int kIters = K / 32;

#pragma unroll
    for (int s = 0; s < 2; s++) {
        if (s < kIters) {
            cp16(&SA[s][lr][lc], aSrc + (size_t)(s * 32) * lda);
            cp16(&SB[s][lr][lc], bSrc + (size_t)(s * 32) * ldb);
        }
        cp_commit();
    }

    for (int it = 0; it < kIters; it++) {
        cp_wait1();
        __syncthreads();
        if (it + 2 < kIters) {
            const int st = (it + 2) % 3;
            cp16(&SA[st][lr][lc], aSrc + (size_t)((it + 2) * 32) * lda);
            cp16(&SB[st][lr][lc], bSrc + (size_t)((it + 2) * 32) * ldb);
        }
        cp_commit();

        const int st = it % 3;
#pragma unroll
        for (int kc = 0; kc < 2; kc++) {
            uint32_t a[2][4], b[2][2];
#pragma unroll
            for (int i = 0; i < 2; i++) {
                const int mb = wm * 32 + i * 16;
                uint32_t addr = smem_u32(&SA[st][kc * 16 + arow][mb + acol]);
                asm volatile(
                    "ldmatrix.sync.aligned.m8n8.x4.trans.shared.b16 {%0,%1,%2,%3},[%4];"
                    : "=r"(a[i][0]), "=r"(a[i][1]), "=r"(a[i][2]), "=r"(a[i][3])
                    : "r"(addr));
            }
#pragma unroll
            for (int j = 0; j < 2; j++) {
                const int nb = wn * 16 + j * 8;
                uint32_t addr = smem_u32(&SB[st][kc * 16 + brow][nb]);
                asm volatile(
                    "ldmatrix.sync.aligned.m8n8.x2.trans.shared.b16 {%0,%1},[%2];"
                    : "=r"(b[j][0]), "=r"(b[j][1])
                    : "r"(addr));
            }
#pragma unroll
            for (int i = 0; i < 2; i++)
#pragma unroll
                for (int j = 0; j < 2; j++)
                    mma_bf16(acc[i][j], a[i][0], a[i][1], a[i][2], a[i][3],
                             b[j][0], b[j][1]);
        }
    }

    const int g = lane >> 2, t = lane & 3;
#pragma unroll
    for (int i = 0; i < 2; i++) {
        const int rb = m0 + wm * 32 + i * 16 + g;
#pragma unroll
        for (int j = 0; j < 2; j++) {
            const int c = n0 + wn * 16 + j * 8 + t * 2;
            *(__nv_bfloat162*)(C + (size_t)rb * ldc + c)       = __floats2bfloat162_rn(acc[i][j][0], acc[i][j][1]);
            *(__nv_bfloat162*)(C + (size_t)(rb + 8) * ldc + c) = __floats2bfloat162_rn(acc[i][j][2], acc[i][j][3]);
        }
    }
}

// ---------------------------------------------------------------------------
extern "C" void kernel_launch(void* const* d_in, const int* in_sizes, int n_in,
                              void* d_out, int out_size)
{
    const float* x  = (const float*)d_in[0];
    const float* Wa = (const float*)d_in[1];
    const float* Wb = (const float*)d_in[2];
    const float* Wu = (const float*)d_in[3];
    const float* bu = (const float*)d_in[4];
    const float* Wr = (const float*)d_in[5];
    float* out = (float*)d_out;

    __nv_bfloat16 *W, *xb, *proj, *Mt;
    float *s, *br;
    cudaGetSymbolAddress((void**)&W,    g_W);
    cudaGetSymbolAddress((void**)&xb,   g_xb);
    cudaGetSymbolAddress((void**)&proj, g_proj);
    cudaGetSymbolAddress((void**)&Mt,   g_Mt);
    cudaGetSymbolAddress((void**)&s,    g_s);
    cudaGetSymbolAddress((void**)&br,   g_br);

    const int SMEM = 6 * NTSTG * 2;   // 61440 B
    cudaFuncSetAttribute(gemm_nt<1, false>, cudaFuncAttributeMaxDynamicSharedMemorySize, SMEM);
    cudaFuncSetAttribute(gemm_nt<4, true>,  cudaFuncAttributeMaxDynamicSharedMemorySize, SMEM);

    // 0) setup: x->bf16, pack interleaved Wa/Wb, Wur, br, zero s  (one launch)
    setup<<<SETUP_BLOCKS, 256>>>(x, Wa, Wb, Wu, Wr, bu, xb, W, br, s);

    // 1) proj = x @ Wpacked^T; epilogue de-interleaves alpha/beta, fuses
    //    s[r] = alpha_r . beta_r (atomics), adds br on uW cols.
    gemm_nt<1, false><<<dim3(PJ / 128, ROWS / 128, 1), 256, SMEM>>>(
        xb, FEAT, 0, W, FEAT, 0, proj, PJ, 0, FEAT,
        br, s, nullptr, 0, nullptr, 0, 0, nullptr, 0, 0);

    // 2) per-batch Mt2[h,f] = sum_n uW[n,h] * beta[n,f]
    gemm_tt<<<dim3(FEAT / 64, FEAT / 64, BATCH), 256>>>(
        proj + 512, PJ, (long)SEQ * PJ,
        proj + 256, PJ, (long)SEQ * PJ,
        Mt, FEAT, (long)FEAT * FEAT, SEQ);

    // 3) out = (alpha @ Mt2^T - s*uW)/1024 + x   (fp32 out)
    gemm_nt<4, true><<<dim3(FEAT / 128, SEQ / 128, BATCH), 256, SMEM>>>(
        proj, PJ, (long)SEQ * PJ,
        Mt, FEAT, (long)FEAT * FEAT,
        out, FEAT, (long)SEQ * FEAT, FEAT,
        nullptr, nullptr, s, (long)SEQ, proj + 512, PJ, (long)SEQ * PJ,
        x, FEAT, (long)SEQ * FEAT);
}

// round 7
// speedup vs baseline: 1.1084x; 1.1084x over previous
#include <cuda_runtime.h>
#include <cuda_bf16.h>
#include <cstdint>

#define BATCH 16
#define SEQ   1024
#define FEAT  256
#define ROWS  (BATCH * SEQ)     // 16384
#define PJ    768               // 3 * FEAT (alpha | beta | uW)
#define MTSZ  (BATCH * FEAT * FEAT)

// ---- scratch (__device__ globals; no allocation allowed) ----
// g_W rows [0,512): 8-col-group interleaved Wa/Wb. packed row p:
//   f = (p>>4)*8 + (p&7), sel = (p>>3)&1 (0=Wa, 1=Wb)
// rows [512,768): Wur = W_r @ W_u
__device__ __align__(16) __nv_bfloat16 g_W   [PJ * FEAT];
__device__ __align__(16) __nv_bfloat16 g_xb  [ROWS * FEAT];     // x in bf16
__device__ __align__(16) __nv_bfloat16 g_proj[ROWS * PJ];       // [r][alpha|beta|uW]
__device__ __align__(16) float         g_Mtp [4 * MTSZ];        // split-K partials
__device__ __align__(16) __nv_bfloat16 g_Mt  [MTSZ];            // Mt2[h][f] per batch
__device__ float g_s [ROWS];
__device__ float g_br[FEAT];

// ---------------------------------------------------------------------------
__device__ __forceinline__ uint32_t smem_u32(const void* p) {
    return (uint32_t)__cvta_generic_to_shared(p);
}
__device__ __forceinline__ void cp16(void* s, const void* g) {
    asm volatile("cp.async.ca.shared.global [%0], [%1], 16;\n"
                 :: "r"(smem_u32(s)), "l"(g));
}
__device__ __forceinline__ void cp_commit() {
    asm volatile("cp.async.commit_group;\n");
}
__device__ __forceinline__ void cp_wait1() {
    asm volatile("cp.async.wait_group 1;\n");
}
__device__ __forceinline__ void mma_bf16(float c[4],
        uint32_t a0, uint32_t a1, uint32_t a2, uint32_t a3,
        uint32_t b0, uint32_t b1) {
    asm volatile(
        "mma.sync.aligned.m16n8k16.row.col.f32.bf16.bf16.f32 "
        "{%0,%1,%2,%3},{%4,%5,%6,%7},{%8,%9},{%0,%1,%2,%3};"
        : "+f"(c[0]), "+f"(c[1]), "+f"(c[2]), "+f"(c[3])
        : "r"(a0), "r"(a1), "r"(a2), "r"(a3), "r"(b0), "r"(b1));
}
__device__ __forceinline__ void ldm4(uint32_t r[4], const void* p) {
    asm volatile(
        "ldmatrix.sync.aligned.m8n8.x4.shared.b16 {%0,%1,%2,%3},[%4];"
        : "=r"(r[0]), "=r"(r[1]), "=r"(r[2]), "=r"(r[3])
        : "r"(smem_u32(p)));
}

// ---------------------------------------------------------------------------
// setup: one launch, independent block groups.
//  [0,2048)      x -> bf16 (8 elems/thread)
//  [2048,2112)   pack Wa/Wb 8-col-group interleaved -> g_W rows [0,512)
//  [2112,2144)   Wur = W_r @ W_u (fp32 SIMT) -> g_W rows [512,768)
//  2144          br = W_r @ b
//  [2145,2161)   zero g_s
// ---------------------------------------------------------------------------
#define SETUP_BLOCKS 2161

__global__ __launch_bounds__(256)
void setup(const float* __restrict__ x,
           const float* __restrict__ Wa, const float* __restrict__ Wb,
           const float* __restrict__ Wu, const float* __restrict__ Wr,
           const float* __restrict__ bu,
           __nv_bfloat16* __restrict__ xb, __nv_bfloat16* __restrict__ W,
           float* __restrict__ br, float* __restrict__ s)
{
    const int blk = blockIdx.x, tid = threadIdx.x;
    if (blk < 2048) {
        int i = (blk * 256 + tid) * 8;
        float4 v0 = *(const float4*)(x + i);
        float4 v1 = *(const float4*)(x + i + 4);
        __nv_bfloat162 p0 = __floats2bfloat162_rn(v0.x, v0.y);
        __nv_bfloat162 p1 = __floats2bfloat162_rn(v0.z, v0.w);
        __nv_bfloat162 p2 = __floats2bfloat162_rn(v1.x, v1.y);
        __nv_bfloat162 p3 = __floats2bfloat162_rn(v1.z, v1.w);
        uint4 o = make_uint4(*(uint32_t*)&p0, *(uint32_t*)&p1,
                             *(uint32_t*)&p2, *(uint32_t*)&p3);
        *(uint4*)(xb + i) = o;
    } else if (blk < 2112) {
        // pack: packed row p -> f = (p>>4)*8 + (p&7), sel = (p>>3)&1
        int j0 = ((blk - 2048) * 256 + tid) * 8;    // [0, 131072)
        int p = j0 >> 8, col = j0 & 255;
        int f = ((p >> 4) << 3) + (p & 7);
        const float* src = (((p >> 3) & 1) ? Wb : Wa) + (size_t)f * FEAT + col;
        float4 v0 = *(const float4*)src;
        float4 v1 = *(const float4*)(src + 4);
        __nv_bfloat162 p0 = __floats2bfloat162_rn(v0.x, v0.y);
        __nv_bfloat162 p1 = __floats2bfloat162_rn(v0.z, v0.w);
        __nv_bfloat162 p2 = __floats2bfloat162_rn(v1.x, v1.y);
        __nv_bfloat162 p3 = __floats2bfloat162_rn(v1.z, v1.w);
        uint4 o = make_uint4(*(uint32_t*)&p0, *(uint32_t*)&p1,
                             *(uint32_t*)&p2, *(uint32_t*)&p3);
        *(uint4*)(W + j0) = o;
    } else if (blk < 2144) {
        // Wur[h,f] = sum_g Wr[h,g] * Wu[g,f], 8 h-rows per block, thread = f
        __shared__ float sWr[8][FEAT];
        const int h0 = (blk - 2112) * 8;
        for (int k = 0; k < 8; k++)
            sWr[k][tid] = Wr[(size_t)(h0 + k) * FEAT + tid];
        __syncthreads();
        float acc[8] = {};
        const int f = tid;
#pragma unroll 4
        for (int g = 0; g < FEAT; g++) {
            float wu = Wu[(size_t)g * FEAT + f];
#pragma unroll
            for (int h = 0; h < 8; h++)
                acc[h] += sWr[h][g] * wu;
        }
#pragma unroll
        for (int h = 0; h < 8; h++)
            W[(size_t)(512 + h0 + h) * FEAT + f] = __float2bfloat16(acc[h]);
    } else if (blk == 2144) {
        __shared__ float bsh[FEAT];
        bsh[tid] = bu[tid];
        __syncthreads();
        const float* wr = Wr + (size_t)tid * FEAT;
        float acc = 0.0f;
#pragma unroll 8
        for (int g = 0; g < FEAT; g += 4) {
            float4 w = *(const float4*)(wr + g);
            acc += w.x * bsh[g] + w.y * bsh[g + 1]
                 + w.z * bsh[g + 2] + w.w * bsh[g + 3];
        }
        br[tid] = acc;
    } else {
        int i = ((blk - 2145) * 256 + tid) * 4;
        *(float4*)(s + i) = make_float4(0.f, 0.f, 0.f, 0.f);
    }
}

// ---------------------------------------------------------------------------
// NT GEMM: C[M,N] = A[M,K] * B[N,K]^T, bf16 tensor core.
// BM=128, BN=128, BK=32, 256 threads, warp tile 64x32,
// 3-stage cp.async pipeline, ldmatrix fragment loads. smem dynamic 61440 B.
// EPI 1 (proj): col blocks < 512 hold interleaved alpha/beta (8-col groups);
//   epilogue de-interleaves (vectorized bf16x2 stores) and fuses
//   s[r] += alpha_r . beta_r via register-local products + atomics.
//   col blocks >= 512: uW, add br.
// EPI 4 (final): (acc - s[r]*uW[r,c])/1024 + x[r,c], fp32 out.
// ---------------------------------------------------------------------------
#define NTSTG 5120

template<int EPI, bool OUT_F32>
__global__ __launch_bounds__(256)
void gemm_nt(const __nv_bfloat16* __restrict__ A, int lda, long sA,
             const __nv_bfloat16* __restrict__ B, int ldb, long sB,
             void* __restrict__ Cp, int ldc, long sC, int K,
             const float* __restrict__ bias,
             float* __restrict__ sout,
             const float* __restrict__ sdot, long sS,
             const __nv_bfloat16* __restrict__ U, int ldu, long sU,
             const float* __restrict__ Xres, int ldx, long sX)
{
    extern __shared__ __align__(16) __nv_bfloat16 sm[];
    __nv_bfloat16* Ab = sm;
    __nv_bfloat16* Bb = sm + 3 * NTSTG;

    const int z = blockIdx.z;
    A += (size_t)z * sA;
    B += (size_t)z * sB;

    const int tid  = threadIdx.x;
    const int lane = tid & 31, warp = tid >> 5;
    const int wm = warp & 1, wn = warp >> 1;
    const int g = lane >> 2, t = lane & 3;
    const int row0 = blockIdx.y * 128, col0 = blockIdx.x * 128;

    const int lr = tid >> 1, lc = (tid & 1) * 16;

    const int aoff = (wm * 64 + (lane & 15)) * 40 + ((lane >> 4) << 3);
    const int boff = (wn * 32 + (lane & 7) + ((lane >> 3) & 1) * 8) * 40
                   + ((lane >> 4) << 3);

    float acc[4][4][4] = {};
    const int kIters = K / 32;

    const __nv_bfloat16* aSrc = A + (size_t)(row0 + lr) * lda + lc;
    const __nv_bfloat16* bSrc = B + (size_t)(col0 + lr) * ldb + lc;

#pragma unroll
    for (int s = 0; s < 2; s++) {
        if (s < kIters) {
            __nv_bfloat16* as = Ab + s * NTSTG + lr * 40 + lc;
            __nv_bfloat16* bs = Bb + s * NTSTG + lr * 40 + lc;
            cp16(as,     aSrc + s * 32);
            cp16(as + 8, aSrc + s * 32 + 8);
            cp16(bs,     bSrc + s * 32);
            cp16(bs + 8, bSrc + s * 32 + 8);
        }
        cp_commit();
    }

    for (int it = 0; it < kIters; it++) {
        cp_wait1();
        __syncthreads();
        if (it + 2 < kIters) {
            const int st = (it + 2) % 3;
            __nv_bfloat16* as = Ab + st * NTSTG + lr * 40 + lc;
            __nv_bfloat16* bs = Bb + st * NTSTG + lr * 40 + lc;
            cp16(as,     aSrc + (it + 2) * 32);
            cp16(as + 8, aSrc + (it + 2) * 32 + 8);
            cp16(bs,     bSrc + (it + 2) * 32);
            cp16(bs + 8, bSrc + (it + 2) * 32 + 8);
        }
        cp_commit();

        const int st = it % 3;
        const __nv_bfloat16* As = Ab + st * NTSTG;
        const __nv_bfloat16* Bs = Bb + st * NTSTG;
#pragma unroll
        for (int kc = 0; kc < 2; kc++) {
            uint32_t a[4][4];
#pragma unroll
            for (int i = 0; i < 4; i++)
                ldm4(a[i], As + aoff + i * 16 * 40 + kc * 16);
            uint32_t bm[2][4];
#pragma unroll
            for (int jp = 0; jp < 2; jp++)
                ldm4(bm[jp], Bs + boff + jp * 16 * 40 + kc * 16);
#pragma unroll
            for (int j = 0; j < 4; j++) {
                const uint32_t b0 = bm[j >> 1][j & 1];
                const uint32_t b1 = bm[j >> 1][(j & 1) + 2];
#pragma unroll
                for (int i = 0; i < 4; i++)
                    mma_bf16(acc[i][j], a[i][0], a[i][1], a[i][2], a[i][3], b0, b1);
            }
        }
    }

    // ---- epilogue ----
    const float invN = 1.0f / 1024.0f;
    const float* sd           = (EPI == 4) ? sdot + (size_t)z * sS : nullptr;
    const __nv_bfloat16* Uz   = (EPI == 4) ? U + (size_t)z * sU : nullptr;
    const float* Xz           = (EPI == 4) ? Xres + (size_t)z * sX : nullptr;
    float*          Cf = OUT_F32 ? (float*)Cp + (size_t)z * sC : nullptr;
    __nv_bfloat16*  Cb = OUT_F32 ? nullptr : (__nv_bfloat16*)Cp + (size_t)z * sC;

    if (EPI == 1 && col0 < 512) {
        // 8-col-group interleaved alpha/beta: j even = alpha, j odd = beta,
        // pairs (0,1) and (2,3) share the same f range per lane.
#pragma unroll
        for (int i = 0; i < 4; i++) {
            const int rb = row0 + wm * 64 + i * 16 + g;
            float pd0 = 0.0f, pd1 = 0.0f;
#pragma unroll
            for (int jp = 0; jp < 2; jp++) {
                pd0 += acc[i][2*jp][0] * acc[i][2*jp+1][0]
                     + acc[i][2*jp][1] * acc[i][2*jp+1][1];
                pd1 += acc[i][2*jp][2] * acc[i][2*jp+1][2]
                     + acc[i][2*jp][3] * acc[i][2*jp+1][3];
            }
#pragma unroll
            for (int j = 0; j < 4; j++) {
                const int c   = col0 + wn * 32 + j * 8 + t * 2;
                const int dst = ((c >> 3) & 1) * 256 + ((c >> 4) << 3) + (c & 7);
                *(__nv_bfloat162*)(Cb + (size_t)rb * ldc + dst) =
                    __floats2bfloat162_rn(acc[i][j][0], acc[i][j][1]);
                *(__nv_bfloat162*)(Cb + (size_t)(rb + 8) * ldc + dst) =
                    __floats2bfloat162_rn(acc[i][j][2], acc[i][j][3]);
            }
            pd0 += __shfl_xor_sync(0xFFFFFFFFu, pd0, 1);
            pd0 += __shfl_xor_sync(0xFFFFFFFFu, pd0, 2);
            pd1 += __shfl_xor_sync(0xFFFFFFFFu, pd1, 1);
            pd1 += __shfl_xor_sync(0xFFFFFFFFu, pd1, 2);
            if (t == 0) {
                atomicAdd(&sout[rb],     pd0);
                atomicAdd(&sout[rb + 8], pd1);
            }
        }
        return;
    }

#pragma unroll
    for (int i = 0; i < 4; i++) {
        const int rb = row0 + wm * 64 + i * 16 + g;
#pragma unroll
        for (int j = 0; j < 4; j++) {
            const int c = col0 + wn * 32 + j * 8 + t * 2;
            float v00 = acc[i][j][0], v01 = acc[i][j][1];
            float v10 = acc[i][j][2], v11 = acc[i][j][3];
            if (EPI == 1) {
                float b0 = bias[c - 512], b1 = bias[c - 511];
                v00 += b0; v01 += b1; v10 += b0; v11 += b1;
            } else if (EPI == 4) {
                float s0 = sd[rb], s1 = sd[rb + 8];
                __nv_bfloat162 u0 = *(const __nv_bfloat162*)(Uz + (size_t)rb * ldu + c);
                __nv_bfloat162 u1 = *(const __nv_bfloat162*)(Uz + (size_t)(rb + 8) * ldu + c);
                float2 fu0 = __bfloat1622float2(u0);
                float2 fu1 = __bfloat1622float2(u1);
                float2 x0 = *(const float2*)(Xz + (size_t)rb * ldx + c);
                float2 x1 = *(const float2*)(Xz + (size_t)(rb + 8) * ldx + c);
                v00 = (v00 - s0 * fu0.x) * invN + x0.x;
                v01 = (v01 - s0 * fu0.y) * invN + x0.y;
                v10 = (v10 - s1 * fu1.x) * invN + x1.x;
                v11 = (v11 - s1 * fu1.y) * invN + x1.y;
            }
            if (OUT_F32) {
                *(float2*)(Cf + (size_t)rb * ldc + c)       = make_float2(v00, v01);
                *(float2*)(Cf + (size_t)(rb + 8) * ldc + c) = make_float2(v10, v11);
            } else {
                *(__nv_bfloat162*)(Cb + (size_t)rb * ldc + c)       = __floats2bfloat162_rn(v00, v01);
                *(__nv_bfloat162*)(Cb + (size_t)(rb + 8) * ldc + c) = __floats2bfloat162_rn(v10, v11);
            }
        }
    }
}

// ---------------------------------------------------------------------------
// Split-K TT GEMM for Mt: C[m,n] += sum_k uW[k,m] * beta[k,n] over K chunk.
// grid (4, 4, 64): z = batch*4 + chunk. fp32 partials, no atomics.
// BM=64, BN=64, BK=32, 8 K-iters per block.
// ---------------------------------------------------------------------------
__global__ __launch_bounds__(256)
void gemm_tt_sk(const __nv_bfloat16* __restrict__ Auw,   // proj + 512
                const __nv_bfloat16* __restrict__ Bbeta, // proj + 256
                float* __restrict__ C)                   // g_Mtp
{
    const int z = blockIdx.z;
    const int batch = z >> 2, chunk = z & 3;
    const size_t srcOff = (size_t)batch * SEQ * PJ + (size_t)chunk * 256 * PJ;
    const __nv_bfloat16* A = Auw + srcOff;
    const __nv_bfloat16* B = Bbeta + srcOff;
    C += (size_t)chunk * MTSZ + (size_t)batch * FEAT * FEAT;

    __shared__ __align__(16) __nv_bfloat16 SA[3][32][72];
    __shared__ __align__(16) __nv_bfloat16 SB[3][32][72];

    const int tid = threadIdx.x, lane = tid & 31, warp = tid >> 5;
    const int wm = warp >> 2, wn = warp & 3;
    const int m0 = blockIdx.y * 64, n0 = blockIdx.x * 64;

    const int lr = tid >> 3, lc = (tid & 7) * 8;

    float acc[2][2][4] = {};

    const int arow = ((lane >> 4) << 3) + (lane & 7);
    const int acol = ((lane >> 3) & 1) << 3;
    const int brow = (((lane >> 3) & 1) << 3) + (lane & 7);

    const __nv_bfloat16* aSrc = A + (size_t)lr * PJ + m0 + lc;
    const __nv_bfloat16* bSrc = B + (size_t)lr * PJ + n0 + lc;
    const int kIters = 8;

#pragma unroll
    for (int s = 0; s < 2; s++) {
        cp16(&SA[s][lr][lc], aSrc + (size_t)(s * 32) * PJ);
        cp16(&SB[s][lr][lc], bSrc + (size_t)(s * 32) * PJ);
        cp_commit();
    }

    for (int it = 0; it < kIters; it++) {
        cp_wait1();
        __syncthreads();
        if (it + 2 < kIters) {
            const int st = (it + 2) % 3;
            cp16(&SA[st][lr][lc], aSrc + (size_t)((it + 2) * 32) * PJ);
            cp16(&SB[st][lr][lc], bSrc + (size_t)((it + 2) * 32) * PJ);
        }
        cp_commit();

        const int st = it % 3;
#pragma unroll
        for (int kc = 0; kc < 2; kc++) {
            uint32_t a[2][4], b[2][2];
#pragma unroll
            for (int i = 0; i < 2; i++) {
                const int mb = wm * 32 + i * 16;
                uint32_t addr = smem_u32(&SA[st][kc * 16 + arow][mb + acol]);
                asm volatile(
                    "ldmatrix.sync.aligned.m8n8.x4.trans.shared.b16 {%0,%1,%2,%3},[%4];"
                    : "=r"(a[i][0]), "=r"(a[i][1]), "=r"(a[i][2]), "=r"(a[i][3])
                    : "r"(addr));
            }
#pragma unroll
            for (int j = 0; j < 2; j++) {
                const int nb = wn * 16 + j * 8;
                uint32_t addr = smem_u32(&SB[st][kc * 16 + brow][nb]);
                asm volatile(
                    "ldmatrix.sync.aligned.m8n8.x2.trans.shared.b16 {%0,%1},[%2];"
                    : "=r"(b[j][0]), "=r"(b[j][1])
                    : "r"(addr));
            }
#pragma unroll
            for (int i = 0; i < 2; i++)
#pragma unroll
                for (int j = 0; j < 2; j++)
                    mma_bf16(acc[i][j], a[i][0], a[i][1], a[i][2], a[i][3],
                             b[j][0], b[j][1]);
        }
    }

    const int g = lane >> 2, t = lane & 3;
#pragma unroll
    for (int i = 0; i < 2; i++) {
        const int rb = m0 + wm * 32 + i * 16 + g;
#pragma unroll
        for (int j = 0; j < 2; j++) {
            const int c = n0 + wn * 16 + j * 8 + t * 2;
            *(float2*)(C + (size_t)rb * FEAT + c)       = make_float2(acc[i][j][0], acc[i][j][1]);
            *(float2*)(C + (size_t)(rb + 8) * FEAT + c) = make_float2(acc[i][j][2], acc[i][j][3]);
        }
    }
}

// ---------------------------------------------------------------------------
// mt_reduce: Mt = bf16(sum of 4 fp32 partials). 4 elems/thread.
// ---------------------------------------------------------------------------
__global__ __launch_bounds__(256)
void mt_reduce(const float* __restrict__ p, __nv_bfloat16* __restrict__ o)
{
    int i = (blockIdx.x * 256 + threadIdx.x) * 4;
    float4 a = *(const float4*)(p + i);
    float4 b = *(const float4*)(p + MTSZ + i);
    float4 c = *(const float4*)(p + 2 * MTSZ + i);
    float4 d = *(const float4*)(p + 3 * MTSZ + i);
    float r0 = a.x + b.x + c.x + d.x;
    float r1 = a.y + b.y + c.y + d.y;
    float r2 = a.z + b.z + c.z + d.z;
    float r3 = a.w + b.w + c.w + d.w;
    __nv_bfloat162 lo = __floats2bfloat162_rn(r0, r1);
    __nv_bfloat162 hi = __floats2bfloat162_rn(r2, r3);
    *(uint2*)(o + i) = make_uint2(*(uint32_t*)&lo, *(uint32_t*)&hi);
}

// ---------------------------------------------------------------------------
extern "C" void kernel_launch(void* const* d_in, const int* in_sizes, int n_in,
                              void* d_out, int out_size)
{
    const float* x  = (const float*)d_in[0];
    const float* Wa = (const float*)d_in[1];
    const float* Wb = (const float*)d_in[2];
    const float* Wu = (const float*)d_in[3];
    const float* bu = (const float*)d_in[4];
    const float* Wr = (const float*)d_in[5];
    float* out = (float*)d_out;

    __nv_bfloat16 *W, *xb, *proj, *Mt;
    float *s, *br, *Mtp;
    cudaGetSymbolAddress((void**)&W,    g_W);
    cudaGetSymbolAddress((void**)&xb,   g_xb);
    cudaGetSymbolAddress((void**)&proj, g_proj);
    cudaGetSymbolAddress((void**)&Mt,   g_Mt);
    cudaGetSymbolAddress((void**)&Mtp,  g_Mtp);
    cudaGetSymbolAddress((void**)&s,    g_s);
    cudaGetSymbolAddress((void**)&br,   g_br);

    const int SMEM = 6 * NTSTG * 2;   // 61440 B
    cudaFuncSetAttribute(gemm_nt<1, false>, cudaFuncAttributeMaxDynamicSharedMemorySize, SMEM);
    cudaFuncSetAttribute(gemm_nt<4, true>,  cudaFuncAttributeMaxDynamicSharedMemorySize, SMEM);

    // 0) setup: x->bf16, pack Wa/Wb (8-col interleave), Wur, br, zero s
    setup<<<SETUP_BLOCKS, 256>>>(x, Wa, Wb, Wu, Wr, bu, xb, W, br, s);

    // 1) proj = x @ Wpacked^T; epilogue de-interleaves alpha/beta,
    //    fuses s[r] = alpha_r . beta_r, adds br on uW cols.
    gemm_nt<1, false><<<dim3(PJ / 128, ROWS / 128, 1), 256, SMEM>>>(
        xb, FEAT, 0, W, FEAT, 0, proj, PJ, 0, FEAT,
        br, s, nullptr, 0, nullptr, 0, 0, nullptr, 0, 0);

    // 2) Mt partials: Mtp[chunk][batch][h][f] = sum over K-chunk
    gemm_tt_sk<<<dim3(4, 4, 64), 256>>>(proj + 512, proj + 256, Mtp);

    // 2b) Mt = sum of partials (bf16)
    mt_reduce<<<MTSZ / 1024, 256>>>(Mtp, Mt);

    // 3) out = (alpha @ Mt^T - s*uW)/1024 + x   (fp32 out)
    gemm_nt<4, true><<<dim3(FEAT / 128, SEQ / 128, BATCH), 256, SMEM>>>(
        proj, PJ, (long)SEQ * PJ,
        Mt, FEAT, (long)FEAT * FEAT,
        out, FEAT, (long)SEQ * FEAT, FEAT,
        nullptr, nullptr, s, (long)SEQ, proj + 512, PJ, (long)SEQ * PJ,
        x, FEAT, (long)SEQ * FEAT);
}

// round 9
// speedup vs baseline: 1.1256x; 1.0156x over previous
#include <cuda_runtime.h>
#include <cuda_bf16.h>
#include <cstdint>

#define BATCH 16
#define SEQ   1024
#define FEAT  256
#define ROWS  (BATCH * SEQ)     // 16384
#define PJ    768               // 3 * FEAT (alpha | beta | uW)
#define MTSZ  (BATCH * FEAT * FEAT)   // 1,048,576 elems

// ---- scratch (__device__ globals; no allocation allowed) ----
// g_W rows [0,256)=Wa, [256,512)=Wb, [512,768)=Wur (all [g][f] bf16)
__device__ __align__(16) __nv_bfloat16 g_W   [PJ * FEAT];
__device__ __align__(16) __nv_bfloat16 g_xb  [ROWS * FEAT];     // x in bf16
__device__ __align__(16) __nv_bfloat16 g_proj[ROWS * PJ];       // [r][alpha|beta|uW]
__device__ __align__(16) __nv_bfloat16 g_Mtp [2 * MTSZ];        // split-K bf16 partials
__device__ __align__(16) __nv_bfloat16 g_Mt  [MTSZ];            // Mt2[h][f] per batch
__device__ float g_s [ROWS];
__device__ float g_br[FEAT];

// ---------------------------------------------------------------------------
__device__ __forceinline__ uint32_t smem_u32(const void* p) {
    return (uint32_t)__cvta_generic_to_shared(p);
}
__device__ __forceinline__ void cp16(void* s, const void* g) {
    asm volatile("cp.async.ca.shared.global [%0], [%1], 16;\n"
                 :: "r"(smem_u32(s)), "l"(g));
}
__device__ __forceinline__ void cp_commit() {
    asm volatile("cp.async.commit_group;\n");
}
__device__ __forceinline__ void cp_wait1() {
    asm volatile("cp.async.wait_group 1;\n");
}
__device__ __forceinline__ void mma_bf16(float c[4],
        uint32_t a0, uint32_t a1, uint32_t a2, uint32_t a3,
        uint32_t b0, uint32_t b1) {
    asm volatile(
        "mma.sync.aligned.m16n8k16.row.col.f32.bf16.bf16.f32 "
        "{%0,%1,%2,%3},{%4,%5,%6,%7},{%8,%9},{%0,%1,%2,%3};"
        : "+f"(c[0]), "+f"(c[1]), "+f"(c[2]), "+f"(c[3])
        : "r"(a0), "r"(a1), "r"(a2), "r"(a3), "r"(b0), "r"(b1));
}
__device__ __forceinline__ void ldm4(uint32_t r[4], const void* p) {
    asm volatile(
        "ldmatrix.sync.aligned.m8n8.x4.shared.b16 {%0,%1,%2,%3},[%4];"
        : "=r"(r[0]), "=r"(r[1]), "=r"(r[2]), "=r"(r[3])
        : "r"(smem_u32(p)));
}

// ---------------------------------------------------------------------------
// setup: one launch, independent block groups.
//  [0,2048)      x -> bf16 (8 elems/thread)
//  [2048,2112)   pack Wa|Wb sequential rows -> g_W [0,512)
//  [2112,2144)   Wur = W_r @ W_u (fp32 SIMT) -> g_W rows [512,768)
//  2144          br = W_r @ b
// ---------------------------------------------------------------------------
#define SETUP_BLOCKS 2145

__global__ __launch_bounds__(256)
void setup(const float* __restrict__ x,
           const float* __restrict__ Wa, const float* __restrict__ Wb,
           const float* __restrict__ Wu, const float* __restrict__ Wr,
           const float* __restrict__ bu,
           __nv_bfloat16* __restrict__ xb, __nv_bfloat16* __restrict__ W,
           float* __restrict__ br)
{
    const int blk = blockIdx.x, tid = threadIdx.x;
    if (blk < 2048) {
        int i = (blk * 256 + tid) * 8;
        float4 v0 = *(const float4*)(x + i);
        float4 v1 = *(const float4*)(x + i + 4);
        __nv_bfloat162 p0 = __floats2bfloat162_rn(v0.x, v0.y);
        __nv_bfloat162 p1 = __floats2bfloat162_rn(v0.z, v0.w);
        __nv_bfloat162 p2 = __floats2bfloat162_rn(v1.x, v1.y);
        __nv_bfloat162 p3 = __floats2bfloat162_rn(v1.z, v1.w);
        uint4 o = make_uint4(*(uint32_t*)&p0, *(uint32_t*)&p1,
                             *(uint32_t*)&p2, *(uint32_t*)&p3);
        *(uint4*)(xb + i) = o;
    } else if (blk < 2112) {
        int j0 = ((blk - 2048) * 256 + tid) * 8;    // [0, 131072)
        int p = j0 >> 8, col = j0 & 255;
        const float* src = (p < 256 ? Wa + (size_t)p * FEAT
                                    : Wb + (size_t)(p - 256) * FEAT) + col;
        float4 v0 = *(const float4*)src;
        float4 v1 = *(const float4*)(src + 4);
        __nv_bfloat162 p0 = __floats2bfloat162_rn(v0.x, v0.y);
        __nv_bfloat162 p1 = __floats2bfloat162_rn(v0.z, v0.w);
        __nv_bfloat162 p2 = __floats2bfloat162_rn(v1.x, v1.y);
        __nv_bfloat162 p3 = __floats2bfloat162_rn(v1.z, v1.w);
        uint4 o = make_uint4(*(uint32_t*)&p0, *(uint32_t*)&p1,
                             *(uint32_t*)&p2, *(uint32_t*)&p3);
        *(uint4*)(W + j0) = o;
    } else if (blk < 2144) {
        // Wur[h,f] = sum_g Wr[h,g] * Wu[g,f], 8 h-rows per block, thread = f
        __shared__ float sWr[8][FEAT];
        const int h0 = (blk - 2112) * 8;
        for (int k = 0; k < 8; k++)
            sWr[k][tid] = Wr[(size_t)(h0 + k) * FEAT + tid];
        __syncthreads();
        float acc[8] = {};
        const int f = tid;
#pragma unroll 4
        for (int g = 0; g < FEAT; g++) {
            float wu = Wu[(size_t)g * FEAT + f];
#pragma unroll
            for (int h = 0; h < 8; h++)
                acc[h] += sWr[h][g] * wu;
        }
#pragma unroll
        for (int h = 0; h < 8; h++)
            W[(size_t)(512 + h0 + h) * FEAT + f] = __float2bfloat16(acc[h]);
    } else {
        __shared__ float bsh[FEAT];
        bsh[tid] = bu[tid];
        __syncthreads();
        const float* wr = Wr + (size_t)tid * FEAT;
        float acc = 0.0f;
#pragma unroll 8
        for (int g = 0; g < FEAT; g += 4) {
            float4 w = *(const float4*)(wr + g);
            acc += w.x * bsh[g] + w.y * bsh[g + 1]
                 + w.z * bsh[g + 2] + w.w * bsh[g + 3];
        }
        br[tid] = acc;
    }
}

// ---------------------------------------------------------------------------
// proj GEMM: C[M,768] = A[M,256] * W[768,256]^T, BM=128, BN=128, BK=32,
// 256 thr, warp tile 64x32, 3-stage cp.async, ldmatrix. +br bias for c>=512.
// ---------------------------------------------------------------------------
#define NTSTG 5120   // 128*40

__global__ __launch_bounds__(256)
void gemm_proj(const __nv_bfloat16* __restrict__ A,
               const __nv_bfloat16* __restrict__ B,
               __nv_bfloat16* __restrict__ C,
               const float* __restrict__ bias)
{
    extern __shared__ __align__(16) __nv_bfloat16 sm[];
    __nv_bfloat16* Ab = sm;
    __nv_bfloat16* Bb = sm + 3 * NTSTG;

    const int tid  = threadIdx.x;
    const int lane = tid & 31, warp = tid >> 5;
    const int wm = warp & 1, wn = warp >> 1;
    const int g = lane >> 2, t = lane & 3;
    const int row0 = blockIdx.y * 128, col0 = blockIdx.x * 128;

    const int lr = tid >> 1, lc = (tid & 1) * 16;

    const int aoff = (wm * 64 + (lane & 15)) * 40 + ((lane >> 4) << 3);
    const int boff = (wn * 32 + (lane & 7) + ((lane >> 3) & 1) * 8) * 40
                   + ((lane >> 4) << 3);

    float acc[4][4][4] = {};
    const int kIters = FEAT / 32;   // 8

    const __nv_bfloat16* aSrc = A + (size_t)(row0 + lr) * FEAT + lc;
    const __nv_bfloat16* bSrc = B + (size_t)(col0 + lr) * FEAT + lc;

#pragma unroll
    for (int s = 0; s < 2; s++) {
        __nv_bfloat16* as = Ab + s * NTSTG + lr * 40 + lc;
        __nv_bfloat16* bs = Bb + s * NTSTG + lr * 40 + lc;
        cp16(as,     aSrc + s * 32);
        cp16(as + 8, aSrc + s * 32 + 8);
        cp16(bs,     bSrc + s * 32);
        cp16(bs + 8, bSrc + s * 32 + 8);
        cp_commit();
    }

    for (int it = 0; it < kIters; it++) {
        cp_wait1();
        __syncthreads();
        if (it + 2 < kIters) {
            const int st = (it + 2) % 3;
            __nv_bfloat16* as = Ab + st * NTSTG + lr * 40 + lc;
            __nv_bfloat16* bs = Bb + st * NTSTG + lr * 40 + lc;
            cp16(as,     aSrc + (it + 2) * 32);
            cp16(as + 8, aSrc + (it + 2) * 32 + 8);
            cp16(bs,     bSrc + (it + 2) * 32);
            cp16(bs + 8, bSrc + (it + 2) * 32 + 8);
        }
        cp_commit();

        const int st = it % 3;
        const __nv_bfloat16* As = Ab + st * NTSTG;
        const __nv_bfloat16* Bs = Bb + st * NTSTG;
#pragma unroll
        for (int kc = 0; kc < 2; kc++) {
            uint32_t a[4][4];
#pragma unroll
            for (int i = 0; i < 4; i++)
                ldm4(a[i], As + aoff + i * 16 * 40 + kc * 16);
            uint32_t bm[2][4];
#pragma unroll
            for (int jp = 0; jp < 2; jp++)
                ldm4(bm[jp], Bs + boff + jp * 16 * 40 + kc * 16);
#pragma unroll
            for (int j = 0; j < 4; j++) {
                const uint32_t b0 = bm[j >> 1][j & 1];
                const uint32_t b1 = bm[j >> 1][(j & 1) + 2];
#pragma unroll
                for (int i = 0; i < 4; i++)
                    mma_bf16(acc[i][j], a[i][0], a[i][1], a[i][2], a[i][3], b0, b1);
            }
        }
    }

#pragma unroll
    for (int i = 0; i < 4; i++) {
        const int rb = row0 + wm * 64 + i * 16 + g;
#pragma unroll
        for (int j = 0; j < 4; j++) {
            const int c = col0 + wn * 32 + j * 8 + t * 2;
            float v00 = acc[i][j][0], v01 = acc[i][j][1];
            float v10 = acc[i][j][2], v11 = acc[i][j][3];
            if (c >= 512) {
                float b0 = bias[c - 512], b1 = bias[c - 511];
                v00 += b0; v01 += b1; v10 += b0; v11 += b1;
            }
            *(__nv_bfloat162*)(C + (size_t)rb * PJ + c)       = __floats2bfloat162_rn(v00, v01);
            *(__nv_bfloat162*)(C + (size_t)(rb + 8) * PJ + c) = __floats2bfloat162_rn(v10, v11);
        }
    }
}

// ---------------------------------------------------------------------------
// final GEMM: out[r,c] = (alpha @ Mt^T - s*uW)/1024 + x, fp32 out.
// BM=128, BN=64, BK=32, 256 thr, 8 warps (4m x 2n), warp tile 32x32.
// grid (FEAT/64=4, SEQ/128=8, BATCH=16) = 512 blocks. static smem 45KB.
// ---------------------------------------------------------------------------
__global__ __launch_bounds__(256)
void gemm_final(const __nv_bfloat16* __restrict__ proj,   // alpha at +0, uW at +512
                const __nv_bfloat16* __restrict__ Mt,
                float* __restrict__ out,
                const float* __restrict__ sdot,
                const float* __restrict__ Xres)
{
    __shared__ __align__(16) __nv_bfloat16 Ab[3][128][40];
    __shared__ __align__(16) __nv_bfloat16 Bb[3][64][40];

    const int z = blockIdx.z;
    const __nv_bfloat16* A  = proj + (size_t)z * SEQ * PJ;          // alpha
    const __nv_bfloat16* B  = Mt   + (size_t)z * FEAT * FEAT;
    const __nv_bfloat16* Uz = proj + (size_t)z * SEQ * PJ + 512;    // uW
    const float* sd = sdot + (size_t)z * SEQ;
    const float* Xz = Xres + (size_t)z * SEQ * FEAT;
    float* Cz = out + (size_t)z * SEQ * FEAT;

    const int tid  = threadIdx.x;
    const int lane = tid & 31, warp = tid >> 5;
    const int wm = warp >> 1, wn = warp & 1;
    const int g = lane >> 2, t = lane & 3;
    const int row0 = blockIdx.y * 128, col0 = blockIdx.x * 64;

    const int ar = tid >> 1, ac = (tid & 1) * 16;   // A: 128 rows x 2 halves
    const int brw = tid >> 2, bc = (tid & 3) * 8;   // B: 64 rows x 4 segs

    const int aoff = (wm * 32 + (lane & 15)) * 40 + ((lane >> 4) << 3);
    const int boff = (wn * 32 + (lane & 7) + ((lane >> 3) & 1) * 8) * 40
                   + ((lane >> 4) << 3);

    float acc[2][4][4] = {};
    const int kIters = FEAT / 32;   // 8

    const __nv_bfloat16* aSrc = A + (size_t)(row0 + ar) * PJ + ac;
    const __nv_bfloat16* bSrc = B + (size_t)(col0 + brw) * FEAT + bc;

#pragma unroll
    for (int s = 0; s < 2; s++) {
        cp16(&Ab[s][ar][ac],     aSrc + s * 32);
        cp16(&Ab[s][ar][ac + 8], aSrc + s * 32 + 8);
        cp16(&Bb[s][brw][bc],    bSrc + s * 32);
        cp_commit();
    }

    for (int it = 0; it < kIters; it++) {
        cp_wait1();
        __syncthreads();
        if (it + 2 < kIters) {
            const int st = (it + 2) % 3;
            cp16(&Ab[st][ar][ac],     aSrc + (it + 2) * 32);
            cp16(&Ab[st][ar][ac + 8], aSrc + (it + 2) * 32 + 8);
            cp16(&Bb[st][brw][bc],    bSrc + (it + 2) * 32);
        }
        cp_commit();

        const int st = it % 3;
        const __nv_bfloat16* As = &Ab[st][0][0];
        const __nv_bfloat16* Bs = &Bb[st][0][0];
#pragma unroll
        for (int kc = 0; kc < 2; kc++) {
            uint32_t a[2][4];
#pragma unroll
            for (int i = 0; i < 2; i++)
                ldm4(a[i], As + aoff + i * 16 * 40 + kc * 16);
            uint32_t bm[2][4];
#pragma unroll
            for (int jp = 0; jp < 2; jp++)
                ldm4(bm[jp], Bs + boff + jp * 16 * 40 + kc * 16);
#pragma unroll
            for (int j = 0; j < 4; j++) {
                const uint32_t b0 = bm[j >> 1][j & 1];
                const uint32_t b1 = bm[j >> 1][(j & 1) + 2];
#pragma unroll
                for (int i = 0; i < 2; i++)
                    mma_bf16(acc[i][j], a[i][0], a[i][1], a[i][2], a[i][3], b0, b1);
            }
        }
    }

    const float invN = 1.0f / 1024.0f;
#pragma unroll
    for (int i = 0; i < 2; i++) {
        const int rb = row0 + wm * 32 + i * 16 + g;
        const float s0 = sd[rb], s1 = sd[rb + 8];
#pragma unroll
        for (int j = 0; j < 4; j++) {
            const int c = col0 + wn * 32 + j * 8 + t * 2;
            __nv_bfloat162 u0 = *(const __nv_bfloat162*)(Uz + (size_t)rb * PJ + c);
            __nv_bfloat162 u1 = *(const __nv_bfloat162*)(Uz + (size_t)(rb + 8) * PJ + c);
            float2 fu0 = __bfloat1622float2(u0);
            float2 fu1 = __bfloat1622float2(u1);
            float2 x0 = *(const float2*)(Xz + (size_t)rb * FEAT + c);
            float2 x1 = *(const float2*)(Xz + (size_t)(rb + 8) * FEAT + c);
            float v00 = (acc[i][j][0] - s0 * fu0.x) * invN + x0.x;
            float v01 = (acc[i][j][1] - s0 * fu0.y) * invN + x0.y;
            float v10 = (acc[i][j][2] - s1 * fu1.x) * invN + x1.x;
            float v11 = (acc[i][j][3] - s1 * fu1.y) * invN + x1.y;
            *(float2*)(Cz + (size_t)rb * FEAT + c)       = make_float2(v00, v01);
            *(float2*)(Cz + (size_t)(rb + 8) * FEAT + c) = make_float2(v10, v11);
        }
    }
}

// ---------------------------------------------------------------------------
// Mt split-K=2 TT GEMM: partial[chunk][b][m][n] = sum_{k in chunk} uW[k,m]*beta[k,n]
// grid (4, 4, 32): z -> batch = z>>1, chunk = z&1. 16 K-iters per block.
// ---------------------------------------------------------------------------
__global__ __launch_bounds__(256)
void gemm_tt_sk(const __nv_bfloat16* __restrict__ Auw,   // proj + 512
                const __nv_bfloat16* __restrict__ Bbeta, // proj + 256
                __nv_bfloat16* __restrict__ C)           // g_Mtp
{
    const int z = blockIdx.z;
    const int batch = z >> 1, chunk = z & 1;
    const size_t srcOff = (size_t)batch * SEQ * PJ + (size_t)chunk * 512 * PJ;
    const __nv_bfloat16* A = Auw + srcOff;
    const __nv_bfloat16* B = Bbeta + srcOff;
    C += (size_t)chunk * MTSZ + (size_t)batch * FEAT * FEAT;

    __shared__ __align__(16) __nv_bfloat16 SA[3][32][72];
    __shared__ __align__(16) __nv_bfloat16 SB[3][32][72];

    const int tid = threadIdx.x, lane = tid & 31, warp = tid >> 5;
    const int wm = warp >> 2, wn = warp & 3;
    const int m0 = blockIdx.y * 64, n0 = blockIdx.x * 64;

    const int lr = tid >> 3, lc = (tid & 7) * 8;

    float acc[2][2][4] = {};

    const int arow = ((lane >> 4) << 3) + (lane & 7);
    const int acol = ((lane >> 3) & 1) << 3;
    const int brow = (((lane >> 3) & 1) << 3) + (lane & 7);

    const __nv_bfloat16* aSrc = A + (size_t)lr * PJ + m0 + lc;
    const __nv_bfloat16* bSrc = B + (size_t)lr * PJ + n0 + lc;
    const int kIters = 16;   // 512 / 32

#pragma unroll
    for (int s = 0; s < 2; s++) {
        cp16(&SA[s][lr][lc], aSrc + (size_t)(s * 32) * PJ);
        cp16(&SB[s][lr][lc], bSrc + (size_t)(s * 32) * PJ);
        cp_commit();
    }

    for (int it = 0; it < kIters; it++) {
        cp_wait1();
        __syncthreads();
        if (it + 2 < kIters) {
            const int st = (it + 2) % 3;
            cp16(&SA[st][lr][lc], aSrc + (size_t)((it + 2) * 32) * PJ);
            cp16(&SB[st][lr][lc], bSrc + (size_t)((it + 2) * 32) * PJ);
        }
        cp_commit();

        const int st = it % 3;
#pragma unroll
        for (int kc = 0; kc < 2; kc++) {
            uint32_t a[2][4], b[2][2];
#pragma unroll
            for (int i = 0; i < 2; i++) {
                const int mb = wm * 32 + i * 16;
                uint32_t addr = smem_u32(&SA[st][kc * 16 + arow][mb + acol]);
                asm volatile(
                    "ldmatrix.sync.aligned.m8n8.x4.trans.shared.b16 {%0,%1,%2,%3},[%4];"
                    : "=r"(a[i][0]), "=r"(a[i][1]), "=r"(a[i][2]), "=r"(a[i][3])
                    : "r"(addr));
            }
#pragma unroll
            for (int j = 0; j < 2; j++) {
                const int nb = wn * 16 + j * 8;
                uint32_t addr = smem_u32(&SB[st][kc * 16 + brow][nb]);
                asm volatile(
                    "ldmatrix.sync.aligned.m8n8.x2.trans.shared.b16 {%0,%1},[%2];"
                    : "=r"(b[j][0]), "=r"(b[j][1])
                    : "r"(addr));
            }
#pragma unroll
            for (int i = 0; i < 2; i++)
#pragma unroll
                for (int j = 0; j < 2; j++)
                    mma_bf16(acc[i][j], a[i][0], a[i][1], a[i][2], a[i][3],
                             b[j][0], b[j][1]);
        }
    }

    const int g = lane >> 2, t = lane & 3;
#pragma unroll
    for (int i = 0; i < 2; i++) {
        const int rb = m0 + wm * 32 + i * 16 + g;
#pragma unroll
        for (int j = 0; j < 2; j++) {
            const int c = n0 + wn * 16 + j * 8 + t * 2;
            *(__nv_bfloat162*)(C + (size_t)rb * FEAT + c)       = __floats2bfloat162_rn(acc[i][j][0], acc[i][j][1]);
            *(__nv_bfloat162*)(C + (size_t)(rb + 8) * FEAT + c) = __floats2bfloat162_rn(acc[i][j][2], acc[i][j][3]);
        }
    }
}

// ---------------------------------------------------------------------------
// mtred2: Mt = bf16(p0 + p1). 8 elems/thread.
// ---------------------------------------------------------------------------
__global__ __launch_bounds__(256)
void mtred2(const __nv_bfloat16* __restrict__ p, __nv_bfloat16* __restrict__ o)
{
    int i = (blockIdx.x * 256 + threadIdx.x) * 8;
    uint4 va = *(const uint4*)(p + i);
    uint4 vb = *(const uint4*)(p + MTSZ + i);
    const __nv_bfloat162* ha = (const __nv_bfloat162*)&va;
    const __nv_bfloat162* hb = (const __nv_bfloat162*)&vb;
    uint4 ov;
    __nv_bfloat162* ho = (__nv_bfloat162*)&ov;
#pragma unroll
    for (int k = 0; k < 4; k++) {
        float2 fa = __bfloat1622float2(ha[k]);
        float2 fb = __bfloat1622float2(hb[k]);
        ho[k] = __floats2bfloat162_rn(fa.x + fb.x, fa.y + fb.y);
    }
    *(uint4*)(o + i) = ov;
}

// ---------------------------------------------------------------------------
// rowdot: s[r] = dot(alpha[r,:], beta[r,:]). 2 rows per warp.
// ---------------------------------------------------------------------------
__global__ __launch_bounds__(256)
void rowdot(const __nv_bfloat16* __restrict__ proj, float* __restrict__ s)
{
    const int warp = threadIdx.x >> 5, lane = threadIdx.x & 31;
    const int row  = blockIdx.x * 16 + warp * 2;
    const __nv_bfloat16* p0 = proj + (size_t)row * PJ + lane * 8;
    const __nv_bfloat16* p1 = p0 + PJ;
    uint4 va0 = *(const uint4*)p0;
    uint4 vb0 = *(const uint4*)(p0 + FEAT);
    uint4 va1 = *(const uint4*)p1;
    uint4 vb1 = *(const uint4*)(p1 + FEAT);
    const __nv_bfloat162* ha0 = (const __nv_bfloat162*)&va0;
    const __nv_bfloat162* hb0 = (const __nv_bfloat162*)&vb0;
    const __nv_bfloat162* ha1 = (const __nv_bfloat162*)&va1;
    const __nv_bfloat162* hb1 = (const __nv_bfloat162*)&vb1;
    float s0 = 0.0f, s1 = 0.0f;
#pragma unroll
    for (int i = 0; i < 4; i++) {
        float2 a0 = __bfloat1622float2(ha0[i]);
        float2 b0 = __bfloat1622float2(hb0[i]);
        float2 a1 = __bfloat1622float2(ha1[i]);
        float2 b1 = __bfloat1622float2(hb1[i]);
        s0 += a0.x * b0.x + a0.y * b0.y;
        s1 += a1.x * b1.x + a1.y * b1.y;
    }
#pragma unroll
    for (int o = 16; o > 0; o >>= 1) {
        s0 += __shfl_xor_sync(0xFFFFFFFFu, s0, o);
        s1 += __shfl_xor_sync(0xFFFFFFFFu, s1, o);
    }
    if (lane == 0) { s[row] = s0; s[row + 1] = s1; }
}

// ---------------------------------------------------------------------------
extern "C" void kernel_launch(void* const* d_in, const int* in_sizes, int n_in,
                              void* d_out, int out_size)
{
    const float* x  = (const float*)d_in[0];
    const float* Wa = (const float*)d_in[1];
    const float* Wb = (const float*)d_in[2];
    const float* Wu = (const float*)d_in[3];
    const float* bu = (const float*)d_in[4];
    const float* Wr = (const float*)d_in[5];
    float* out = (float*)d_out;

    __nv_bfloat16 *W, *xb, *proj, *Mt, *Mtp;
    float *s, *br;
    cudaGetSymbolAddress((void**)&W,    g_W);
    cudaGetSymbolAddress((void**)&xb,   g_xb);
    cudaGetSymbolAddress((void**)&proj, g_proj);
    cudaGetSymbolAddress((void**)&Mt,   g_Mt);
    cudaGetSymbolAddress((void**)&Mtp,  g_Mtp);
    cudaGetSymbolAddress((void**)&s,    g_s);
    cudaGetSymbolAddress((void**)&br,   g_br);

    const int SMEM = 6 * NTSTG * 2;   // 61440 B
    cudaFuncSetAttribute(gemm_proj, cudaFuncAttributeMaxDynamicSharedMemorySize, SMEM);

    // 0) setup: x->bf16, pack Wa|Wb, Wur, br (one launch)
    setup<<<SETUP_BLOCKS, 256>>>(x, Wa, Wb, Wu, Wr, bu, xb, W, br);

    // 1) proj = x @ [Wa|Wb|Wur]^T (+br on uW cols)
    gemm_proj<<<dim3(PJ / 128, ROWS / 128, 1), 256, SMEM>>>(xb, W, proj, br);

    // 2) s[r] = alpha_r . beta_r
    rowdot<<<ROWS / 16, 256>>>(proj, s);

    // 3) Mt partials (split-K=2, bf16)
    gemm_tt_sk<<<dim3(4, 4, 32), 256>>>(proj + 512, proj + 256, Mtp);

    // 3b) Mt = p0 + p1
    mtred2<<<MTSZ / 2048, 256>>>(Mtp, Mt);

    // 4) out = (alpha @ Mt^T - s*uW)/1024 + x   (fp32 out)
    gemm_final<<<dim3(FEAT / 64, SEQ / 128, BATCH), 256>>>(proj, Mt, out, s, x);
}

// round 11
// speedup vs baseline: 1.2954x; 1.1509x over previous
#include <cuda_runtime.h>
#include <cuda_bf16.h>
#include <cstdint>

#define BATCH 16
#define SEQ   1024
#define FEAT  256
#define ROWS  (BATCH * SEQ)     // 16384
#define PJ    768               // 3 * FEAT (alpha | beta | uW)

// ---- scratch (__device__ globals; no allocation allowed) ----
// g_W rows [0,256)=Wa, [256,512)=Wb, [512,768)=Wur (all [g][f] bf16)
__device__ __align__(16) __nv_bfloat16 g_W   [PJ * FEAT];
__device__ __align__(16) __nv_bfloat16 g_xb  [ROWS * FEAT];     // x in bf16
__device__ __align__(16) __nv_bfloat16 g_proj[ROWS * PJ];       // [r][alpha|beta|uW]
__device__ __align__(16) __nv_bfloat16 g_Mt  [BATCH * FEAT * FEAT]; // Mt2[h][f]
__device__ float g_s [ROWS];
__device__ float g_br[FEAT];

// ---------------------------------------------------------------------------
__device__ __forceinline__ uint32_t smem_u32(const void* p) {
    return (uint32_t)__cvta_generic_to_shared(p);
}
__device__ __forceinline__ void cp16(void* s, const void* g) {
    asm volatile("cp.async.ca.shared.global [%0], [%1], 16;\n"
                 :: "r"(smem_u32(s)), "l"(g));
}
__device__ __forceinline__ void cp_commit() {
    asm volatile("cp.async.commit_group;\n");
}
__device__ __forceinline__ void cp_wait1() {
    asm volatile("cp.async.wait_group 1;\n");
}
__device__ __forceinline__ void mma_bf16(float c[4],
        uint32_t a0, uint32_t a1, uint32_t a2, uint32_t a3,
        uint32_t b0, uint32_t b1) {
    asm volatile(
        "mma.sync.aligned.m16n8k16.row.col.f32.bf16.bf16.f32 "
        "{%0,%1,%2,%3},{%4,%5,%6,%7},{%8,%9},{%0,%1,%2,%3};"
        : "+f"(c[0]), "+f"(c[1]), "+f"(c[2]), "+f"(c[3])
        : "r"(a0), "r"(a1), "r"(a2), "r"(a3), "r"(b0), "r"(b1));
}
__device__ __forceinline__ void ldm4(uint32_t r[4], const void* p) {
    asm volatile(
        "ldmatrix.sync.aligned.m8n8.x4.shared.b16 {%0,%1,%2,%3},[%4];"
        : "=r"(r[0]), "=r"(r[1]), "=r"(r[2]), "=r"(r[3])
        : "r"(smem_u32(p)));
}

// ---------------------------------------------------------------------------
// setup: one launch, independent block groups.
//  [0,2048)      x -> bf16 (8 elems/thread)
//  [2048,2112)   pack Wa|Wb sequential rows -> g_W [0,512)
//  [2112,2144)   Wur = W_r @ W_u (fp32 SIMT) -> g_W rows [512,768)
//  2144          br = W_r @ b
// ---------------------------------------------------------------------------
#define SETUP_BLOCKS 2145

__global__ __launch_bounds__(256)
void setup(const float* __restrict__ x,
           const float* __restrict__ Wa, const float* __restrict__ Wb,
           const float* __restrict__ Wu, const float* __restrict__ Wr,
           const float* __restrict__ bu,
           __nv_bfloat16* __restrict__ xb, __nv_bfloat16* __restrict__ W,
           float* __restrict__ br)
{
    const int blk = blockIdx.x, tid = threadIdx.x;
    if (blk < 2048) {
        int i = (blk * 256 + tid) * 8;
        float4 v0 = *(const float4*)(x + i);
        float4 v1 = *(const float4*)(x + i + 4);
        __nv_bfloat162 p0 = __floats2bfloat162_rn(v0.x, v0.y);
        __nv_bfloat162 p1 = __floats2bfloat162_rn(v0.z, v0.w);
        __nv_bfloat162 p2 = __floats2bfloat162_rn(v1.x, v1.y);
        __nv_bfloat162 p3 = __floats2bfloat162_rn(v1.z, v1.w);
        uint4 o = make_uint4(*(uint32_t*)&p0, *(uint32_t*)&p1,
                             *(uint32_t*)&p2, *(uint32_t*)&p3);
        *(uint4*)(xb + i) = o;
    } else if (blk < 2112) {
        int j0 = ((blk - 2048) * 256 + tid) * 8;    // [0, 131072)
        int p = j0 >> 8, col = j0 & 255;
        const float* src = (p < 256 ? Wa + (size_t)p * FEAT
                                    : Wb + (size_t)(p - 256) * FEAT) + col;
        float4 v0 = *(const float4*)src;
        float4 v1 = *(const float4*)(src + 4);
        __nv_bfloat162 p0 = __floats2bfloat162_rn(v0.x, v0.y);
        __nv_bfloat162 p1 = __floats2bfloat162_rn(v0.z, v0.w);
        __nv_bfloat162 p2 = __floats2bfloat162_rn(v1.x, v1.y);
        __nv_bfloat162 p3 = __floats2bfloat162_rn(v1.z, v1.w);
        uint4 o = make_uint4(*(uint32_t*)&p0, *(uint32_t*)&p1,
                             *(uint32_t*)&p2, *(uint32_t*)&p3);
        *(uint4*)(W + j0) = o;
    } else if (blk < 2144) {
        // Wur[h,f] = sum_g Wr[h,g] * Wu[g,f], 8 h-rows per block, thread = f
        __shared__ float sWr[8][FEAT];
        const int h0 = (blk - 2112) * 8;
        for (int k = 0; k < 8; k++)
            sWr[k][tid] = Wr[(size_t)(h0 + k) * FEAT + tid];
        __syncthreads();
        float acc[8] = {};
        const int f = tid;
#pragma unroll 4
        for (int g = 0; g < FEAT; g++) {
            float wu = Wu[(size_t)g * FEAT + f];
#pragma unroll
            for (int h = 0; h < 8; h++)
                acc[h] += sWr[h][g] * wu;
        }
#pragma unroll
        for (int h = 0; h < 8; h++)
            W[(size_t)(512 + h0 + h) * FEAT + f] = __float2bfloat16(acc[h]);
    } else {
        __shared__ float bsh[FEAT];
        bsh[tid] = bu[tid];
        __syncthreads();
        const float* wr = Wr + (size_t)tid * FEAT;
        float acc = 0.0f;
#pragma unroll 8
        for (int g = 0; g < FEAT; g += 4) {
            float4 w = *(const float4*)(wr + g);
            acc += w.x * bsh[g] + w.y * bsh[g + 1]
                 + w.z * bsh[g + 2] + w.w * bsh[g + 3];
        }
        br[tid] = acc;
    }
}

// ---------------------------------------------------------------------------
// NT GEMM (exact R5): C[M,N] = A[M,K] * B[N,K]^T, bf16 tensor core.
// BM=128, BN=128, BK=32, 256 threads, warp tile 64x32,
// 3-stage cp.async pipeline, ldmatrix fragment loads. smem dynamic 61440 B.
// EPI 1 (proj): +br bias for c>=512.
// EPI 4 (final): (acc - s[r]*uW[r,c])/1024 + x[r,c], fp32 out.
// ---------------------------------------------------------------------------
#define NTSTG 5120

template<int EPI, bool OUT_F32>
__global__ __launch_bounds__(256)
void gemm_nt(const __nv_bfloat16* __restrict__ A, int lda, long sA,
             const __nv_bfloat16* __restrict__ B, int ldb, long sB,
             void* __restrict__ Cp, int ldc, long sC, int K,
             const float* __restrict__ bias,
             const float* __restrict__ sdot, long sS,
             const __nv_bfloat16* __restrict__ U, int ldu, long sU,
             const float* __restrict__ Xres, int ldx, long sX)
{
    extern __shared__ __align__(16) __nv_bfloat16 sm[];
    __nv_bfloat16* Ab = sm;
    __nv_bfloat16* Bb = sm + 3 * NTSTG;

    const int z = blockIdx.z;
    A += (size_t)z * sA;
    B += (size_t)z * sB;

    const int tid  = threadIdx.x;
    const int lane = tid & 31, warp = tid >> 5;
    const int wm = warp & 1, wn = warp >> 1;
    const int g = lane >> 2, t = lane & 3;
    const int row0 = blockIdx.y * 128, col0 = blockIdx.x * 128;

    const int lr = tid >> 1, lc = (tid & 1) * 16;

    const int aoff = (wm * 64 + (lane & 15)) * 40 + ((lane >> 4) << 3);
    const int boff = (wn * 32 + (lane & 7) + ((lane >> 3) & 1) * 8) * 40
                   + ((lane >> 4) << 3);

    float acc[4][4][4] = {};
    const int kIters = K / 32;

    const __nv_bfloat16* aSrc = A + (size_t)(row0 + lr) * lda + lc;
    const __nv_bfloat16* bSrc = B + (size_t)(col0 + lr) * ldb + lc;

#pragma unroll
    for (int s = 0; s < 2; s++) {
        if (s < kIters) {
            __nv_bfloat16* as = Ab + s * NTSTG + lr * 40 + lc;
            __nv_bfloat16* bs = Bb + s * NTSTG + lr * 40 + lc;
            cp16(as,     aSrc + s * 32);
            cp16(as + 8, aSrc + s * 32 + 8);
            cp16(bs,     bSrc + s * 32);
            cp16(bs + 8, bSrc + s * 32 + 8);
        }
        cp_commit();
    }

    for (int it = 0; it < kIters; it++) {
        cp_wait1();
        __syncthreads();
        if (it + 2 < kIters) {
            const int st = (it + 2) % 3;
            __nv_bfloat16* as = Ab + st * NTSTG + lr * 40 + lc;
            __nv_bfloat16* bs = Bb + st * NTSTG + lr * 40 + lc;
            cp16(as,     aSrc + (it + 2) * 32);
            cp16(as + 8, aSrc + (it + 2) * 32 + 8);
            cp16(bs,     bSrc + (it + 2) * 32);
            cp16(bs + 8, bSrc + (it + 2) * 32 + 8);
        }
        cp_commit();

        const int st = it % 3;
        const __nv_bfloat16* As = Ab + st * NTSTG;
        const __nv_bfloat16* Bs = Bb + st * NTSTG;
#pragma unroll
        for (int kc = 0; kc < 2; kc++) {
            uint32_t a[4][4];
#pragma unroll
            for (int i = 0; i < 4; i++)
                ldm4(a[i], As + aoff + i * 16 * 40 + kc * 16);
            uint32_t bm[2][4];
#pragma unroll
            for (int jp = 0; jp < 2; jp++)
                ldm4(bm[jp], Bs + boff + jp * 16 * 40 + kc * 16);
#pragma unroll
            for (int j = 0; j < 4; j++) {
                const uint32_t b0 = bm[j >> 1][j & 1];
                const uint32_t b1 = bm[j >> 1][(j & 1) + 2];
#pragma unroll
                for (int i = 0; i < 4; i++)
                    mma_bf16(acc[i][j], a[i][0], a[i][1], a[i][2], a[i][3], b0, b1);
            }
        }
    }

    // ---- epilogue ----
    const float invN = 1.0f / 1024.0f;
    const float* sd           = (EPI == 4) ? sdot + (size_t)z * sS : nullptr;
    const __nv_bfloat16* Uz   = (EPI == 4) ? U + (size_t)z * sU : nullptr;
    const float* Xz           = (EPI == 4) ? Xres + (size_t)z * sX : nullptr;
    float*          Cf = OUT_F32 ? (float*)Cp + (size_t)z * sC : nullptr;
    __nv_bfloat16*  Cb = OUT_F32 ? nullptr : (__nv_bfloat16*)Cp + (size_t)z * sC;

#pragma unroll
    for (int i = 0; i < 4; i++) {
        const int rb = row0 + wm * 64 + i * 16 + g;
#pragma unroll
        for (int j = 0; j < 4; j++) {
            const int c = col0 + wn * 32 + j * 8 + t * 2;
            float v00 = acc[i][j][0], v01 = acc[i][j][1];
            float v10 = acc[i][j][2], v11 = acc[i][j][3];
            if (EPI == 1) {
                if (c >= 512) {
                    float b0 = bias[c - 512], b1 = bias[c - 511];
                    v00 += b0; v01 += b1; v10 += b0; v11 += b1;
                }
            } else if (EPI == 4) {
                float s0 = sd[rb], s1 = sd[rb + 8];
                __nv_bfloat162 u0 = *(const __nv_bfloat162*)(Uz + (size_t)rb * ldu + c);
                __nv_bfloat162 u1 = *(const __nv_bfloat162*)(Uz + (size_t)(rb + 8) * ldu + c);
                float2 fu0 = __bfloat1622float2(u0);
                float2 fu1 = __bfloat1622float2(u1);
                float2 x0 = *(const float2*)(Xz + (size_t)rb * ldx + c);
                float2 x1 = *(const float2*)(Xz + (size_t)(rb + 8) * ldx + c);
                v00 = (v00 - s0 * fu0.x) * invN + x0.x;
                v01 = (v01 - s0 * fu0.y) * invN + x0.y;
                v10 = (v10 - s1 * fu1.x) * invN + x1.x;
                v11 = (v11 - s1 * fu1.y) * invN + x1.y;
            }
            if (OUT_F32) {
                *(float2*)(Cf + (size_t)rb * ldc + c)       = make_float2(v00, v01);
                *(float2*)(Cf + (size_t)(rb + 8) * ldc + c) = make_float2(v10, v11);
            } else {
                *(__nv_bfloat162*)(Cb + (size_t)rb * ldc + c)       = __floats2bfloat162_rn(v00, v01);
                *(__nv_bfloat162*)(Cb + (size_t)(rb + 8) * ldc + c) = __floats2bfloat162_rn(v10, v11);
            }
        }
    }
}

// ---------------------------------------------------------------------------
// mt_rowdot: ONE launch, two independent roles (both read proj only).
//  blocks z <  16: exact R5 gemm_tt — Mt[h,f] = sum_n uW[n,h]*beta[n,f],
//                  batch = z, tile (m0,n0) from (y,x). K = 1024.
//  blocks z >= 16: exact R5 rowdot — s[r] = alpha_r . beta_r, 16 rows/block.
// grid (4, 4, 16 + 64) = 256 Mt blocks + 1024 rowdot blocks.
// ---------------------------------------------------------------------------
__global__ __launch_bounds__(256)
void mt_rowdot(const __nv_bfloat16* __restrict__ proj,
               __nv_bfloat16* __restrict__ Mt,
               float* __restrict__ s)
{
    if (blockIdx.z >= BATCH) {
        // ---- rowdot role ----
        const int idx  = ((int)blockIdx.z - BATCH) * 16 + blockIdx.y * 4 + blockIdx.x;
        const int warp = threadIdx.x >> 5, lane = threadIdx.x & 31;
        const int row  = idx * 16 + warp * 2;
        const __nv_bfloat16* p0 = proj + (size_t)row * PJ + lane * 8;
        const __nv_bfloat16* p1 = p0 + PJ;
        uint4 va0 = *(const uint4*)p0;
        uint4 vb0 = *(const uint4*)(p0 + FEAT);
        uint4 va1 = *(const uint4*)p1;
        uint4 vb1 = *(const uint4*)(p1 + FEAT);
        const __nv_bfloat162* ha0 = (const __nv_bfloat162*)&va0;
        const __nv_bfloat162* hb0 = (const __nv_bfloat162*)&vb0;
        const __nv_bfloat162* ha1 = (const __nv_bfloat162*)&va1;
        const __nv_bfloat162* hb1 = (const __nv_bfloat162*)&vb1;
        float s0 = 0.0f, s1 = 0.0f;
#pragma unroll
        for (int i = 0; i < 4; i++) {
            float2 a0 = __bfloat1622float2(ha0[i]);
            float2 b0 = __bfloat1622float2(hb0[i]);
            float2 a1 = __bfloat1622float2(ha1[i]);
            float2 b1 = __bfloat1622float2(hb1[i]);
            s0 += a0.x * b0.x + a0.y * b0.y;
            s1 += a1.x * b1.x + a1.y * b1.y;
        }
#pragma unroll
        for (int o = 16; o > 0; o >>= 1) {
            s0 += __shfl_xor_sync(0xFFFFFFFFu, s0, o);
            s1 += __shfl_xor_sync(0xFFFFFFFFu, s1, o);
        }
        if (lane == 0) { s[row] = s0; s[row + 1] = s1; }
        return;
    }

    // ---- Mt role (exact R5 gemm_tt) ----
    __shared__ __align__(16) __nv_bfloat16 SA[3][32][72];
    __shared__ __align__(16) __nv_bfloat16 SB[3][32][72];

    const int z = blockIdx.z;
    const __nv_bfloat16* A = proj + 512 + (size_t)z * SEQ * PJ;   // uW
    const __nv_bfloat16* B = proj + 256 + (size_t)z * SEQ * PJ;   // beta
    __nv_bfloat16* C = Mt + (size_t)z * FEAT * FEAT;

    const int tid = threadIdx.x, lane = tid & 31, warp = tid >> 5;
    const int wm = warp >> 2, wn = warp & 3;
    const int m0 = blockIdx.y * 64, n0 = blockIdx.x * 64;

    const int lr = tid >> 3, lc = (tid & 7) * 8;

    float acc[2][2][4] = {};

    const int arow = ((lane >> 4) << 3) + (lane & 7);
    const int acol = ((lane >> 3) & 1) << 3;
    const int brow = (((lane >> 3) & 1) << 3) + (lane & 7);

    const __nv_bfloat16* aSrc = A + (size_t)lr * PJ + m0 + lc;
    const __nv_bfloat16* bSrc = B + (size_t)lr * PJ + n0 + lc;
    const int kIters = SEQ / 32;   // 32

#pragma unroll
    for (int st = 0; st < 2; st++) {
        cp16(&SA[st][lr][lc], aSrc + (size_t)(st * 32) * PJ);
        cp16(&SB[st][lr][lc], bSrc + (size_t)(st * 32) * PJ);
        cp_commit();
    }

    for (int it = 0; it < kIters; it++) {
        cp_wait1();
        __syncthreads();
        if (it + 2 < kIters) {
            const int st = (it + 2) % 3;
            cp16(&SA[st][lr][lc], aSrc + (size_t)((it + 2) * 32) * PJ);
            cp16(&SB[st][lr][lc], bSrc + (size_t)((it + 2) * 32) * PJ);
        }
        cp_commit();

        const int st = it % 3;
#pragma unroll
        for (int kc = 0; kc < 2; kc++) {
            uint32_t a[2][4], b[2][2];
#pragma unroll
            for (int i = 0; i < 2; i++) {
                const int mb = wm * 32 + i * 16;
                uint32_t addr = smem_u32(&SA[st][kc * 16 + arow][mb + acol]);
                asm volatile(
                    "ldmatrix.sync.aligned.m8n8.x4.trans.shared.b16 {%0,%1,%2,%3},[%4];"
                    : "=r"(a[i][0]), "=r"(a[i][1]), "=r"(a[i][2]), "=r"(a[i][3])
                    : "r"(addr));
            }
#pragma unroll
            for (int j = 0; j < 2; j++) {
                const int nb = wn * 16 + j * 8;
                uint32_t addr = smem_u32(&SB[st][kc * 16 + brow][nb]);
                asm volatile(
                    "ldmatrix.sync.aligned.m8n8.x2.trans.shared.b16 {%0,%1},[%2];"
                    : "=r"(b[j][0]), "=r"(b[j][1])
                    : "r"(addr));
            }
#pragma unroll
            for (int i = 0; i < 2; i++)
#pragma unroll
                for (int j = 0; j < 2; j++)
                    mma_bf16(acc[i][j], a[i][0], a[i][1], a[i][2], a[i][3],
                             b[j][0], b[j][1]);
        }
    }

    const int g = lane >> 2, t = lane & 3;
#pragma unroll
    for (int i = 0; i < 2; i++) {
        const int rb = m0 + wm * 32 + i * 16 + g;
#pragma unroll
        for (int j = 0; j < 2; j++) {
            const int c = n0 + wn * 16 + j * 8 + t * 2;
            *(__nv_bfloat162*)(C + (size_t)rb * FEAT + c)       = __floats2bfloat162_rn(acc[i][j][0], acc[i][j][1]);
            *(__nv_bfloat162*)(C + (size_t)(rb + 8) * FEAT + c) = __floats2bfloat162_rn(acc[i][j][2], acc[i][j][3]);
        }
    }
}

// ---------------------------------------------------------------------------
extern "C" void kernel_launch(void* const* d_in, const int* in_sizes, int n_in,
                              void* d_out, int out_size)
{
    const float* x  = (const float*)d_in[0];
    const float* Wa = (const float*)d_in[1];
    const float* Wb = (const float*)d_in[2];
    const float* Wu = (const float*)d_in[3];
    const float* bu = (const float*)d_in[4];
    const float* Wr = (const float*)d_in[5];
    float* out = (float*)d_out;

    __nv_bfloat16 *W, *xb, *proj, *Mt;
    float *s, *br;
    cudaGetSymbolAddress((void**)&W,    g_W);
    cudaGetSymbolAddress((void**)&xb,   g_xb);
    cudaGetSymbolAddress((void**)&proj, g_proj);
    cudaGetSymbolAddress((void**)&Mt,   g_Mt);
    cudaGetSymbolAddress((void**)&s,    g_s);
    cudaGetSymbolAddress((void**)&br,   g_br);

    const int SMEM = 6 * NTSTG * 2;   // 61440 B
    cudaFuncSetAttribute(gemm_nt<1, false>, cudaFuncAttributeMaxDynamicSharedMemorySize, SMEM);
    cudaFuncSetAttribute(gemm_nt<4, true>,  cudaFuncAttributeMaxDynamicSharedMemorySize, SMEM);

    // 0) setup: x->bf16, pack Wa|Wb, Wur, br (one launch)
    setup<<<SETUP_BLOCKS, 256>>>(x, Wa, Wb, Wu, Wr, bu, xb, W, br);

    // 1) proj = x @ [Wa|Wb|Wur]^T (+br on uW cols)
    gemm_nt<1, false><<<dim3(PJ / 128, ROWS / 128, 1), 256, SMEM>>>(
        xb, FEAT, 0, W, FEAT, 0, proj, PJ, 0, FEAT,
        br, nullptr, 0, nullptr, 0, 0, nullptr, 0, 0);

    // 2) Mt (z<16) + rowdot (z>=16) in one launch — independent roles
    mt_rowdot<<<dim3(4, 4, BATCH + 64), 256>>>(proj, Mt, s);

    // 3) out = (alpha @ Mt^T - s*uW)/1024 + x   (fp32 out)
    gemm_nt<4, true><<<dim3(FEAT / 128, SEQ / 128, BATCH), 256, SMEM>>>(
        proj, PJ, (long)SEQ * PJ,
        Mt, FEAT, (long)FEAT * FEAT,
        out, FEAT, (long)SEQ * FEAT, FEAT,
        nullptr, s, (long)SEQ, proj + 512, PJ, (long)SEQ * PJ,
        x, FEAT, (long)SEQ * FEAT);
}